// round 15
// baseline (speedup 1.0000x reference)
#include <cuda_runtime.h>
#include <cuda_fp16.h>
#include <math.h>
#include <float.h>
#include <stdint.h>

// ---------------- problem constants ----------------
#define R4    4           // fold regions
#define HH    64          // input feature H
#define WW0   216         // input feature W
#define HWP   (HH*WW0)    // 13824 pixels
#define HF    32          // folded H
#define WF    108         // folded W
#define KP    (HF*WF)     // 3456 pixels per region
#define C64   64          // channels
#define NP    8192        // points
#define MCAP  4096        // M = N / FOLD_H
#define MPAD  4608        // padded rows for centers
#define NCH2  5           // interleaved subtile stride

// ---------------- scratch (device globals; no allocation) ----------------
__device__ float  g_featP[R4][KP][C64];   // folded feat, pixel-major
__device__ float  g_valP [R4][KP][C64];   // folded value, pixel-major
__device__ __half g_fh16 [R4][KP][C64];   // feat fp16-hi
__device__ __half g_fl16 [R4][KP][C64];   // feat fp16-lo
__device__ float  g_invx [R4][KP];        // 1/max(||feat_pixel||,1e-12)
__device__ float4 g_bp   [R4][MPAD][16];  // centers packed: slot (s,t4) -> {b0h,b1h,b0l,b1l} half2s
__device__ float  g_vc   [R4][MCAP][C64]; // value centers
__device__ int    g_cnt  [R4];
__device__ float  g_ppx  [R4][MCAP];
__device__ float  g_ppy  [R4][MCAP];
__device__ int    g_pr   [NP];
__device__ int    g_ppos [NP];
__device__ float  g_bestv[R4][NCH2][KP];
__device__ int    g_bestm[R4][NCH2][KP];
__device__ float  g_agg  [R4][MCAP][C64];
__device__ float  g_den  [R4][MCAP];

// ---------------- helpers ----------------
__device__ __forceinline__ void split_f16(float v, __half& hi, __half& lo) {
    hi = __float2half_rn(v);
    lo = __float2half_rn(v - __half2float(hi));
}
__device__ __forceinline__ uint32_t pack_h2(__half a, __half b) {
    __half2 h = __halves2half2(a, b);
    return *reinterpret_cast<uint32_t*>(&h);
}
__device__ __forceinline__ void mma_f16(float c[4], const uint32_t a[4], uint32_t b0, uint32_t b1) {
    asm volatile(
        "mma.sync.aligned.m16n8k16.row.col.f32.f16.f16.f32 "
        "{%0,%1,%2,%3}, {%4,%5,%6,%7}, {%8,%9}, {%0,%1,%2,%3};"
        : "+f"(c[0]), "+f"(c[1]), "+f"(c[2]), "+f"(c[3])
        : "r"(a[0]), "r"(a[1]), "r"(a[2]), "r"(a[3]), "r"(b0), "r"(b1));
}
__device__ __forceinline__ int region_of(float px, float py) {
    if (px > 0.0f && px <= 1296.0f && py > 0.0f && py <= 384.0f)
        return ((py > 192.0f) ? 2 : 0) + ((px > 648.0f) ? 1 : 0);
    return -1;
}

// ---------------- Kernel A: 1x1 conv + fold + fp16 split + inv-norm; block 216 = point partition ----------------
__global__ __launch_bounds__(256) void kA(const float* __restrict__ x,
                                          const float* __restrict__ Wf, const float* __restrict__ bf,
                                          const float* __restrict__ Wv, const float* __restrict__ bv,
                                          const float* __restrict__ pts) {
    int tx = threadIdx.x;

    if (blockIdx.x == 216) {
        // ---- point region partition, chunk-sequential coalesced scan (stable, chunk-major = n order) ----
        __shared__ unsigned long long warpTot[8];
        __shared__ unsigned long long baseSh;
        int widx = tx >> 5, lane = tx & 31;
        if (tx == 0) baseSh = 0ull;
        __syncthreads();
        for (int ch = 0; ch < 32; ch++) {
            int n = ch * 256 + tx;
            float px = pts[2 * n], py = pts[2 * n + 1];
            int ri = region_of(px, py);
            unsigned long long item = (ri >= 0) ? (1ull << (16 * ri)) : 0ull;
            unsigned long long incl = item;
            #pragma unroll
            for (int off = 1; off < 32; off <<= 1) {
                unsigned long long v = __shfl_up_sync(0xffffffffu, incl, off);
                if (lane >= off) incl += v;
            }
            if (lane == 31) warpTot[widx] = incl;
            unsigned long long base = baseSh;
            __syncthreads();
            unsigned long long wpre = 0ull;
            for (int w = 0; w < widx; w++) wpre += warpTot[w];
            unsigned long long ex = base + wpre + (incl - item);
            if (ri >= 0) {
                int pos = (int)((ex >> (16 * ri)) & 0xFFFF);
                g_pr[n] = ri; g_ppos[n] = pos;
                if (pos < MCAP) { g_ppx[ri][pos] = px; g_ppy[ri][pos] = py; }
            } else { g_pr[n] = -1; g_ppos[n] = 0; }
            if (tx == 255) baseSh = base + wpre + incl;
            __syncthreads();
        }
        if (tx == 0) {
            unsigned long long tot = baseSh;
            #pragma unroll
            for (int r = 0; r < 4; r++) g_cnt[r] = (int)((tot >> (16 * r)) & 0xFFFF);
        }
        return;
    }

    __shared__ float xs [64][68];
    __shared__ float wfs[64][68];
    __shared__ float wvs[64][68];
    int p0 = blockIdx.x * 64;

    #pragma unroll
    for (int j = 0; j < 16; j++) {
        int idx = tx + j * 256;
        int o = idx >> 6, c = idx & 63;
        wfs[c][o] = Wf[idx];
        wvs[c][o] = Wv[idx];
    }
    #pragma unroll
    for (int j = 0; j < 16; j++) {
        int idx = tx + j * 256;
        int c = idx >> 6, pl = idx & 63;
        xs[c][pl] = x[c * HWP + p0 + pl];
    }
    __syncthreads();
    int o  = tx & 63;
    int pg = tx >> 6;
    float accf[16], accv[16];
    float bfo = bf[o], bvo = bv[o];
    #pragma unroll
    for (int i = 0; i < 16; i++) { accf[i] = bfo; accv[i] = bvo; }
    #pragma unroll
    for (int c = 0; c < 64; c++) {
        float wfv = wfs[c][o];
        float wvv = wvs[c][o];
        float4 x0 = *reinterpret_cast<const float4*>(&xs[c][pg * 16]);
        float4 x1 = *reinterpret_cast<const float4*>(&xs[c][pg * 16 + 4]);
        float4 x2 = *reinterpret_cast<const float4*>(&xs[c][pg * 16 + 8]);
        float4 x3 = *reinterpret_cast<const float4*>(&xs[c][pg * 16 + 12]);
        float xv[16] = {x0.x, x0.y, x0.z, x0.w, x1.x, x1.y, x1.z, x1.w,
                        x2.x, x2.y, x2.z, x2.w, x3.x, x3.y, x3.z, x3.w};
        #pragma unroll
        for (int i = 0; i < 16; i++) {
            accf[i] += wfv * xv[i];
            accv[i] += wvv * xv[i];
        }
    }
    #pragma unroll
    for (int i = 0; i < 16; i++) {
        int p = p0 + pg * 16 + i;
        int h = p / WW0, w = p % WW0;
        int r = ((h >= HF) ? 2 : 0) + ((w >= WF) ? 1 : 0);
        int loc = (h & 31) * WF + (w >= WF ? w - WF : w);
        g_featP[r][loc][o] = accf[i];
        g_valP [r][loc][o] = accv[i];
        __half hh, ll;
        split_f16(accf[i], hh, ll);
        g_fh16[r][loc][o] = hh;
        g_fl16[r][loc][o] = ll;
    }
    __syncthreads();
    #pragma unroll
    for (int i = 0; i < 16; i++) wfs[pg * 16 + i][o] = accf[i] * accf[i];
    __syncthreads();
    {
        int pl = tx >> 2, q = tx & 3;
        float s = 0.f;
        #pragma unroll
        for (int j = 0; j < 16; j++) s += wfs[pl][q * 16 + j];
        s += __shfl_xor_sync(0xffffffffu, s, 1);
        s += __shfl_xor_sync(0xffffffffu, s, 2);
        if (q == 0) {
            int p = p0 + pl;
            int h = p / WW0, w = p % WW0;
            int r = ((h >= HF) ? 2 : 0) + ((w >= WF) ? 1 : 0);
            int loc = (h & 31) * WF + (w >= WF ? w - WF : w);
            g_invx[r][loc] = 1.0f / fmaxf(sqrtf(s), 1e-12f);
        }
    }
}

// ---------------- Kernel D: bilinear gather + fp16 pack; high blocks also zero agg/den ----------------
__global__ __launch_bounds__(256) void kD(const float* __restrict__ sim_alpha) {
    __shared__ __half sh_h[8][64];
    __shared__ __half sh_l[8][64];
    int r = blockIdx.y;
    if (blockIdx.x >= 288) {
        int slice = (blockIdx.x - 288) + 288 * r;           // 0..1151
        int t = slice * 256 + threadIdx.x;                   // 0..294911
        const int nagg4 = R4 * MCAP * C64 / 4;               // 262144
        if (t < nagg4) reinterpret_cast<float4*>(&g_agg[0][0][0])[t] = make_float4(0.f, 0.f, 0.f, 0.f);
        if (t < R4 * MCAP) (&g_den[0][0])[t] = 0.f;
    }
    int cnt = min(g_cnt[r], MCAP);
    int Mr = cnt + (cnt < MCAP ? 1 : 0);
    int lim = ((Mr + 127) >> 7) << 7;
    int w = threadIdx.x >> 5;
    int m = blockIdx.x * 8 + w;
    int lane = threadIdx.x & 31;
    if (m >= lim) return;
    if (m >= Mr) {
        if (lane < 16) g_bp[r][m][lane] = make_float4(0.f, 0.f, 0.f, 0.f);
        return;
    }
    float f0, f1, v0 = 0.f, v1 = 0.f;
    if (m == cnt) {
        f0 = g_featP[r][0][lane];
        f1 = g_featP[r][0][lane + 32];
    } else {
        float px = g_ppx[r][m], py = g_ppy[r][m];
        float gx = ((px / 1295.0f) * 2.0f - 1.0f + 1.0f) * 54.0f - 0.5f;
        float gy = ((py / 383.0f)  * 2.0f - 1.0f + 1.0f) * 16.0f - 0.5f;
        float x0 = floorf(gx), y0 = floorf(gy);
        float wx = gx - x0, wy = gy - y0;
        int ix0 = (int)fminf(fmaxf(x0,        0.f), 107.f);
        int ix1 = (int)fminf(fmaxf(x0 + 1.0f, 0.f), 107.f);
        int iy0 = (int)fminf(fmaxf(y0,        0.f), 31.f);
        int iy1 = (int)fminf(fmaxf(y0 + 1.0f, 0.f), 31.f);
        float w00 = (1.f - wx) * (1.f - wy), w01 = wx * (1.f - wy);
        float w10 = (1.f - wx) * wy,         w11 = wx * wy;
        int p00 = iy0 * WF + ix0, p01 = iy0 * WF + ix1;
        int p10 = iy1 * WF + ix0, p11 = iy1 * WF + ix1;
        f0 = w00 * g_featP[r][p00][lane]      + w01 * g_featP[r][p01][lane]
           + w10 * g_featP[r][p10][lane]      + w11 * g_featP[r][p11][lane];
        f1 = w00 * g_featP[r][p00][lane + 32] + w01 * g_featP[r][p01][lane + 32]
           + w10 * g_featP[r][p10][lane + 32] + w11 * g_featP[r][p11][lane + 32];
        v0 = w00 * g_valP[r][p00][lane]       + w01 * g_valP[r][p01][lane]
           + w10 * g_valP[r][p10][lane]       + w11 * g_valP[r][p11][lane];
        v1 = w00 * g_valP[r][p00][lane + 32]  + w01 * g_valP[r][p01][lane + 32]
           + w10 * g_valP[r][p10][lane + 32]  + w11 * g_valP[r][p11][lane + 32];
    }
    float ss = f0 * f0 + f1 * f1;
    #pragma unroll
    for (int off = 16; off > 0; off >>= 1) ss += __shfl_xor_sync(0xffffffffu, ss, off);
    float inv = 1.0f / fmaxf(sqrtf(ss), 1e-12f);
    float a = sim_alpha[0] * inv;
    __half h0, l0, h1, l1;
    split_f16(a * f0, h0, l0);
    split_f16(a * f1, h1, l1);
    sh_h[w][lane]      = h0;  sh_l[w][lane]      = l0;
    sh_h[w][lane + 32] = h1;  sh_l[w][lane + 32] = l1;
    __syncwarp();
    if (lane < 16) {
        int s = lane >> 2, tt = lane & 3;
        int kb = s * 16 + 2 * tt;
        uint32_t b0h = pack_h2(sh_h[w][kb],     sh_h[w][kb + 1]);
        uint32_t b1h = pack_h2(sh_h[w][kb + 8], sh_h[w][kb + 9]);
        uint32_t b0l = pack_h2(sh_l[w][kb],     sh_l[w][kb + 1]);
        uint32_t b1l = pack_h2(sh_l[w][kb + 8], sh_l[w][kb + 9]);
        g_bp[r][m][lane] = make_float4(__uint_as_float(b0h), __uint_as_float(b1h),
                                       __uint_as_float(b0l), __uint_as_float(b1l));
    }
    if (m < cnt) {
        g_vc[r][m][lane]      = v0;
        g_vc[r][m][lane + 32] = v1;
    }
}

// ---------------- Kernel E: fp16 3-term m16n8k16 GEMM + fused partial argmax ----------------
#define BSTR 20
__global__ __launch_bounds__(256, 2) void kE5() {
    extern __shared__ float4 Bp[];
    int tid = threadIdx.x;
    int wid = tid >> 5, lane = tid & 31;
    int gid = lane >> 2, t4 = lane & 3;
    int r = blockIdx.z, y = blockIdx.y;
    int k0 = blockIdx.x * 128;
    int cnt = min(g_cnt[r], MCAP);
    int Mr = cnt + (cnt < MCAP ? 1 : 0);
    int nsub = (Mr + 127) >> 7;
    int row0 = k0 + wid * 16 + gid;
    int row1 = row0 + 8;

    float best0 = -FLT_MAX, best1 = -FLT_MAX;
    int   bi0 = 0x7fffffff, bi1 = 0x7fffffff;

    if (y < nsub) {
        uint32_t Ah[4][4], Al[4][4];
        #pragma unroll
        for (int s = 0; s < 4; s++) {
            int kk = s * 16 + 2 * t4;
            Ah[s][0] = *reinterpret_cast<const uint32_t*>(&g_fh16[r][row0][kk]);
            Ah[s][1] = *reinterpret_cast<const uint32_t*>(&g_fh16[r][row1][kk]);
            Ah[s][2] = *reinterpret_cast<const uint32_t*>(&g_fh16[r][row0][kk + 8]);
            Ah[s][3] = *reinterpret_cast<const uint32_t*>(&g_fh16[r][row1][kk + 8]);
            Al[s][0] = *reinterpret_cast<const uint32_t*>(&g_fl16[r][row0][kk]);
            Al[s][1] = *reinterpret_cast<const uint32_t*>(&g_fl16[r][row1][kk]);
            Al[s][2] = *reinterpret_cast<const uint32_t*>(&g_fl16[r][row0][kk + 8]);
            Al[s][3] = *reinterpret_cast<const uint32_t*>(&g_fl16[r][row1][kk + 8]);
        }

        for (int ns = y; ns < nsub; ns += NCH2) {
            int m0 = ns * 128;
            __syncthreads();
            #pragma unroll
            for (int it = 0; it < 8; it++) {
                int e = tid + it * 256;
                int brow = e >> 4, slot = e & 15;
                Bp[brow * BSTR + slot] = g_bp[r][m0 + brow][slot];
            }
            __syncthreads();

            #pragma unroll
            for (int half = 0; half < 2; half++) {
                float c[8][4];
                #pragma unroll
                for (int nt = 0; nt < 8; nt++)
                    #pragma unroll
                    for (int j = 0; j < 4; j++) c[nt][j] = 0.f;

                const float4* bbase = Bp + (half * 64 + gid) * BSTR + t4;
                #pragma unroll
                for (int s = 0; s < 4; s++) {
                    const float4* bks = bbase + s * 4;
                    #pragma unroll
                    for (int nt = 0; nt < 8; nt++) {
                        float4 v = bks[nt * 8 * BSTR];
                        uint32_t b0h = __float_as_uint(v.x);
                        uint32_t b1h = __float_as_uint(v.y);
                        uint32_t b0l = __float_as_uint(v.z);
                        uint32_t b1l = __float_as_uint(v.w);
                        mma_f16(c[nt], Ah[s], b0h, b1h);
                        mma_f16(c[nt], Ah[s], b0l, b1l);
                        mma_f16(c[nt], Al[s], b0h, b1h);
                    }
                }

                int cbase = m0 + half * 64 + t4 * 2;
                #pragma unroll
                for (int nt = 0; nt < 8; nt++) {
                    int col0 = cbase + nt * 8;
                    int col1 = col0 + 1;
                    if (col0 < Mr) {
                        if (c[nt][0] > best0) { best0 = c[nt][0]; bi0 = col0; }
                        if (c[nt][2] > best1) { best1 = c[nt][2]; bi1 = col0; }
                    }
                    if (col1 < Mr) {
                        if (c[nt][1] > best0) { best0 = c[nt][1]; bi0 = col1; }
                        if (c[nt][3] > best1) { best1 = c[nt][3]; bi1 = col1; }
                    }
                }
            }
        }
    }

    #pragma unroll
    for (int off = 1; off <= 2; off <<= 1) {
        float ov0 = __shfl_xor_sync(0xffffffffu, best0, off);
        int   om0 = __shfl_xor_sync(0xffffffffu, bi0,   off);
        float ov1 = __shfl_xor_sync(0xffffffffu, best1, off);
        int   om1 = __shfl_xor_sync(0xffffffffu, bi1,   off);
        if (ov0 > best0 || (ov0 == best0 && om0 < bi0)) { best0 = ov0; bi0 = om0; }
        if (ov1 > best1 || (ov1 == best1 && om1 < bi1)) { best1 = ov1; bi1 = om1; }
    }
    if (t4 == 0) {
        g_bestv[r][y][row0] = best0; g_bestm[r][y][row0] = bi0;
        g_bestv[r][y][row1] = best1; g_bestm[r][y][row1] = bi1;
    }
}

// ---------------- Kernel M: merge partial argmax, sigmoid, scatter-aggregate (8 cols/warp) ----------------
__global__ __launch_bounds__(256) void kM(const float* __restrict__ sim_beta) {
    int r = blockIdx.y;
    int warp = threadIdx.x >> 5, lane = threadIdx.x & 31;
    int colbase = blockIdx.x * 64 + warp * 8;
    int cnt = min(g_cnt[r], MCAP);
    float beta = sim_beta[0];
    #pragma unroll
    for (int i = 0; i < 8; i++) {
        int col = colbase + i;
        float v = -FLT_MAX; int m = 0x7fffffff;
        if (lane < NCH2) { v = g_bestv[r][lane][col]; m = g_bestm[r][lane][col]; }
        #pragma unroll
        for (int off = 4; off > 0; off >>= 1) {
            float ov = __shfl_down_sync(0xffffffffu, v, off);
            int   om = __shfl_down_sync(0xffffffffu, m, off);
            if (ov > v || (ov == v && om < m)) { v = ov; m = om; }
        }
        v = __shfl_sync(0xffffffffu, v, 0);
        m = __shfl_sync(0xffffffffu, m, 0);
        if (m >= cnt) continue;    // dead row won (or empty): column contributes nothing
        float s = beta + v * g_invx[r][col];
        float sim = 1.0f / (1.0f + __expf(-s));
        atomicAdd(&g_agg[r][m][lane],      sim * g_valP[r][col][lane]);
        atomicAdd(&g_agg[r][m][lane + 32], sim * g_valP[r][col][lane + 32]);
        if (lane == 0) atomicAdd(&g_den[r][m], sim);
    }
}

// ---------------- Kernel F: per-point output assembly + projection ----------------
__global__ __launch_bounds__(256) void kF(const float* __restrict__ Wp,
                                          const float* __restrict__ bp,
                                          float* __restrict__ out) {
    __shared__ float so[64][65];
    __shared__ float wp[64][65];
    __shared__ float bsh[64];
    __shared__ int   fl[64];
    int tx = threadIdx.x;
    int n0 = blockIdx.x * 64;
    #pragma unroll
    for (int j = 0; j < 16; j++) {
        int idx = tx + j * 256;
        int o = idx >> 6, c = idx & 63;
        wp[c][o] = Wp[idx];
    }
    if (tx < 64) { bsh[tx] = bp[tx]; fl[tx] = 0; }
    __syncthreads();
    {
        int pl = tx >> 2, cg = tx & 3;
        int n = n0 + pl;
        int r = g_pr[n];
        int lf = 0;
        if (r >= 0) {
            int pos = min(g_ppos[n], MCAP - 1);
            float den = g_den[r][pos] + 1.0f;
            #pragma unroll
            for (int j = 0; j < 16; j++) {
                int c = cg * 16 + j;
                float ov = (g_agg[r][pos][c] + g_vc[r][pos][c]) / den;
                so[pl][c] = ov;
                if (ov != 0.0f) lf = 1;
            }
        } else {
            #pragma unroll
            for (int j = 0; j < 16; j++) so[pl][cg * 16 + j] = 0.0f;
        }
        if (lf) atomicOr(&fl[pl], 1);
    }
    __syncthreads();
    int pl = tx & 63, og = tx >> 6;
    float mask = fl[pl] ? 1.0f : 0.0f;
    float acc[16];
    #pragma unroll
    for (int i = 0; i < 16; i++) acc[i] = 0.f;
    #pragma unroll
    for (int c = 0; c < 64; c++) {
        float xv = so[pl][c];
        #pragma unroll
        for (int i = 0; i < 16; i++) acc[i] += xv * wp[c][og * 16 + i];
    }
    #pragma unroll
    for (int i = 0; i < 16; i++) {
        int o = og * 16 + i;
        out[o * NP + n0 + pl] = (acc[i] + bsh[o]) * mask;
    }
}

// ---------------- launch ----------------
#define KE_SMEM (128 * BSTR * 16)

extern "C" void kernel_launch(void* const* d_in, const int* in_sizes, int n_in,
                              void* d_out, int out_size) {
    const float* points    = (const float*)d_in[0];
    const float* x         = (const float*)d_in[1];
    const float* W_f       = (const float*)d_in[2];
    const float* b_f       = (const float*)d_in[3];
    const float* W_v       = (const float*)d_in[4];
    const float* b_v       = (const float*)d_in[5];
    const float* W_proj    = (const float*)d_in[6];
    const float* b_proj    = (const float*)d_in[7];
    const float* sim_alpha = (const float*)d_in[8];
    const float* sim_beta  = (const float*)d_in[9];
    float* out = (float*)d_out;

    cudaFuncSetAttribute(kE5, cudaFuncAttributeMaxDynamicSharedMemorySize, KE_SMEM);

    kA<<<217, 256>>>(x, W_f, b_f, W_v, b_v, points);
    kD<<<dim3(MPAD / 8, R4), 256>>>(sim_alpha);
    kE5<<<dim3(KP / 128, NCH2, R4), 256, KE_SMEM>>>();
    kM<<<dim3(KP / 64, R4), 256>>>(sim_beta);
    kF<<<NP / 64, 256>>>(W_proj, b_proj, out);
}

// round 16
// speedup vs baseline: 1.0712x; 1.0712x over previous
#include <cuda_runtime.h>
#include <cuda_fp16.h>
#include <math.h>
#include <float.h>
#include <stdint.h>

// ---------------- problem constants ----------------
#define R4    4           // fold regions
#define HH    64          // input feature H
#define WW0   216         // input feature W
#define HWP   (HH*WW0)    // 13824 pixels
#define HF    32          // folded H
#define WF    108         // folded W
#define KP    (HF*WF)     // 3456 pixels per region
#define C64   64          // channels
#define NP    8192        // points
#define MCAP  4096        // M = N / FOLD_H
#define MPAD  4608        // padded rows for centers
#define NCH2  5           // interleaved subtile stride

// ---------------- scratch (device globals; no allocation) ----------------
__device__ float  g_featP[R4][KP][C64];   // folded feat, pixel-major
__device__ float  g_valP [R4][KP][C64];   // folded value, pixel-major
__device__ __half g_fh16 [R4][KP][C64];   // feat fp16-hi
__device__ __half g_fl16 [R4][KP][C64];   // feat fp16-lo
__device__ float  g_invx [R4][KP];        // 1/max(||feat_pixel||,1e-12)
__device__ float4 g_bp   [R4][MPAD][16];  // centers packed: slot (s,t4) -> {b0h,b1h,b0l,b1l} half2s
__device__ float  g_vc   [R4][MCAP][C64]; // value centers
__device__ int    g_cnt  [R4];
__device__ float  g_ppx  [R4][MCAP];
__device__ float  g_ppy  [R4][MCAP];
__device__ int    g_pr   [NP];
__device__ int    g_ppos [NP];
__device__ unsigned long long g_best[R4][KP];  // packed (ordered-float << 32) | ~m
__device__ float  g_agg  [R4][MCAP][C64];
__device__ float  g_den  [R4][MCAP];

// ---------------- helpers ----------------
__device__ __forceinline__ void split_f16(float v, __half& hi, __half& lo) {
    hi = __float2half_rn(v);
    lo = __float2half_rn(v - __half2float(hi));
}
__device__ __forceinline__ uint32_t pack_h2(__half a, __half b) {
    __half2 h = __halves2half2(a, b);
    return *reinterpret_cast<uint32_t*>(&h);
}
__device__ __forceinline__ void mma_f16(float c[4], const uint32_t a[4], uint32_t b0, uint32_t b1) {
    asm volatile(
        "mma.sync.aligned.m16n8k16.row.col.f32.f16.f16.f32 "
        "{%0,%1,%2,%3}, {%4,%5,%6,%7}, {%8,%9}, {%0,%1,%2,%3};"
        : "+f"(c[0]), "+f"(c[1]), "+f"(c[2]), "+f"(c[3])
        : "r"(a[0]), "r"(a[1]), "r"(a[2]), "r"(a[3]), "r"(b0), "r"(b1));
}
__device__ __forceinline__ int region_of(float px, float py) {
    if (px > 0.0f && px <= 1296.0f && py > 0.0f && py <= 384.0f)
        return ((py > 192.0f) ? 2 : 0) + ((px > 648.0f) ? 1 : 0);
    return -1;
}
__device__ __forceinline__ unsigned long long packbm(float v, int m) {
    uint32_t b = __float_as_uint(v);
    uint32_t fk = (b & 0x80000000u) ? ~b : (b | 0x80000000u);   // order-preserving
    return ((unsigned long long)fk << 32) | (uint32_t)(~(uint32_t)m);
}

// ---------------- Kernel A: 1x1 conv + fold + fp16 split + inv-norm; block 216 = point partition ----------------
__global__ __launch_bounds__(256) void kA(const float* __restrict__ x,
                                          const float* __restrict__ Wf, const float* __restrict__ bf,
                                          const float* __restrict__ Wv, const float* __restrict__ bv,
                                          const float* __restrict__ pts) {
    int tx = threadIdx.x;

    if (blockIdx.x == 216) {
        __shared__ unsigned long long warpTot[8];
        __shared__ unsigned long long baseSh;
        int widx = tx >> 5, lane = tx & 31;
        if (tx == 0) baseSh = 0ull;
        __syncthreads();
        for (int ch = 0; ch < 32; ch++) {
            int n = ch * 256 + tx;
            float px = pts[2 * n], py = pts[2 * n + 1];
            int ri = region_of(px, py);
            unsigned long long item = (ri >= 0) ? (1ull << (16 * ri)) : 0ull;
            unsigned long long incl = item;
            #pragma unroll
            for (int off = 1; off < 32; off <<= 1) {
                unsigned long long v = __shfl_up_sync(0xffffffffu, incl, off);
                if (lane >= off) incl += v;
            }
            if (lane == 31) warpTot[widx] = incl;
            unsigned long long base = baseSh;
            __syncthreads();
            unsigned long long wpre = 0ull;
            for (int w = 0; w < widx; w++) wpre += warpTot[w];
            unsigned long long ex = base + wpre + (incl - item);
            if (ri >= 0) {
                int pos = (int)((ex >> (16 * ri)) & 0xFFFF);
                g_pr[n] = ri; g_ppos[n] = pos;
                if (pos < MCAP) { g_ppx[ri][pos] = px; g_ppy[ri][pos] = py; }
            } else { g_pr[n] = -1; g_ppos[n] = 0; }
            if (tx == 255) baseSh = base + wpre + incl;
            __syncthreads();
        }
        if (tx == 0) {
            unsigned long long tot = baseSh;
            #pragma unroll
            for (int r = 0; r < 4; r++) g_cnt[r] = (int)((tot >> (16 * r)) & 0xFFFF);
        }
        return;
    }

    __shared__ float xs [64][68];
    __shared__ float wfs[64][68];
    __shared__ float wvs[64][68];
    int p0 = blockIdx.x * 64;

    #pragma unroll
    for (int j = 0; j < 16; j++) {
        int idx = tx + j * 256;
        int o = idx >> 6, c = idx & 63;
        wfs[c][o] = Wf[idx];
        wvs[c][o] = Wv[idx];
    }
    #pragma unroll
    for (int j = 0; j < 16; j++) {
        int idx = tx + j * 256;
        int c = idx >> 6, pl = idx & 63;
        xs[c][pl] = x[c * HWP + p0 + pl];
    }
    __syncthreads();
    int o  = tx & 63;
    int pg = tx >> 6;
    float accf[16], accv[16];
    float bfo = bf[o], bvo = bv[o];
    #pragma unroll
    for (int i = 0; i < 16; i++) { accf[i] = bfo; accv[i] = bvo; }
    #pragma unroll
    for (int c = 0; c < 64; c++) {
        float wfv = wfs[c][o];
        float wvv = wvs[c][o];
        float4 x0 = *reinterpret_cast<const float4*>(&xs[c][pg * 16]);
        float4 x1 = *reinterpret_cast<const float4*>(&xs[c][pg * 16 + 4]);
        float4 x2 = *reinterpret_cast<const float4*>(&xs[c][pg * 16 + 8]);
        float4 x3 = *reinterpret_cast<const float4*>(&xs[c][pg * 16 + 12]);
        float xv[16] = {x0.x, x0.y, x0.z, x0.w, x1.x, x1.y, x1.z, x1.w,
                        x2.x, x2.y, x2.z, x2.w, x3.x, x3.y, x3.z, x3.w};
        #pragma unroll
        for (int i = 0; i < 16; i++) {
            accf[i] += wfv * xv[i];
            accv[i] += wvv * xv[i];
        }
    }
    #pragma unroll
    for (int i = 0; i < 16; i++) {
        int p = p0 + pg * 16 + i;
        int h = p / WW0, w = p % WW0;
        int r = ((h >= HF) ? 2 : 0) + ((w >= WF) ? 1 : 0);
        int loc = (h & 31) * WF + (w >= WF ? w - WF : w);
        g_featP[r][loc][o] = accf[i];
        g_valP [r][loc][o] = accv[i];
        __half hh, ll;
        split_f16(accf[i], hh, ll);
        g_fh16[r][loc][o] = hh;
        g_fl16[r][loc][o] = ll;
    }
    __syncthreads();
    #pragma unroll
    for (int i = 0; i < 16; i++) wfs[pg * 16 + i][o] = accf[i] * accf[i];
    __syncthreads();
    {
        int pl = tx >> 2, q = tx & 3;
        float s = 0.f;
        #pragma unroll
        for (int j = 0; j < 16; j++) s += wfs[pl][q * 16 + j];
        s += __shfl_xor_sync(0xffffffffu, s, 1);
        s += __shfl_xor_sync(0xffffffffu, s, 2);
        if (q == 0) {
            int p = p0 + pl;
            int h = p / WW0, w = p % WW0;
            int r = ((h >= HF) ? 2 : 0) + ((w >= WF) ? 1 : 0);
            int loc = (h & 31) * WF + (w >= WF ? w - WF : w);
            g_invx[r][loc] = 1.0f / fmaxf(sqrtf(s), 1e-12f);
        }
    }
}

// ---------------- Kernel D: bilinear gather + fp16 pack; high blocks zero agg/den + init g_best ----------------
__global__ __launch_bounds__(256) void kD(const float* __restrict__ sim_alpha) {
    __shared__ __half sh_h[8][64];
    __shared__ __half sh_l[8][64];
    int r = blockIdx.y;
    if (blockIdx.x >= 288) {
        int local = (blockIdx.x - 288) * 256 + threadIdx.x;   // 0..73727 per region
        if (local < KP) g_best[r][local] = 0ull;              // below all real packed keys
        int slice = (blockIdx.x - 288) + 288 * r;             // 0..1151
        int t = slice * 256 + threadIdx.x;                    // 0..294911
        const int nagg4 = R4 * MCAP * C64 / 4;                // 262144
        if (t < nagg4) reinterpret_cast<float4*>(&g_agg[0][0][0])[t] = make_float4(0.f, 0.f, 0.f, 0.f);
        if (t < R4 * MCAP) (&g_den[0][0])[t] = 0.f;
    }
    int cnt = min(g_cnt[r], MCAP);
    int Mr = cnt + (cnt < MCAP ? 1 : 0);
    int lim = ((Mr + 127) >> 7) << 7;
    int w = threadIdx.x >> 5;
    int m = blockIdx.x * 8 + w;
    int lane = threadIdx.x & 31;
    if (m >= lim) return;
    if (m >= Mr) {
        if (lane < 16) g_bp[r][m][lane] = make_float4(0.f, 0.f, 0.f, 0.f);
        return;
    }
    float f0, f1, v0 = 0.f, v1 = 0.f;
    if (m == cnt) {
        f0 = g_featP[r][0][lane];
        f1 = g_featP[r][0][lane + 32];
    } else {
        float px = g_ppx[r][m], py = g_ppy[r][m];
        float gx = ((px / 1295.0f) * 2.0f - 1.0f + 1.0f) * 54.0f - 0.5f;
        float gy = ((py / 383.0f)  * 2.0f - 1.0f + 1.0f) * 16.0f - 0.5f;
        float x0 = floorf(gx), y0 = floorf(gy);
        float wx = gx - x0, wy = gy - y0;
        int ix0 = (int)fminf(fmaxf(x0,        0.f), 107.f);
        int ix1 = (int)fminf(fmaxf(x0 + 1.0f, 0.f), 107.f);
        int iy0 = (int)fminf(fmaxf(y0,        0.f), 31.f);
        int iy1 = (int)fminf(fmaxf(y0 + 1.0f, 0.f), 31.f);
        float w00 = (1.f - wx) * (1.f - wy), w01 = wx * (1.f - wy);
        float w10 = (1.f - wx) * wy,         w11 = wx * wy;
        int p00 = iy0 * WF + ix0, p01 = iy0 * WF + ix1;
        int p10 = iy1 * WF + ix0, p11 = iy1 * WF + ix1;
        f0 = w00 * g_featP[r][p00][lane]      + w01 * g_featP[r][p01][lane]
           + w10 * g_featP[r][p10][lane]      + w11 * g_featP[r][p11][lane];
        f1 = w00 * g_featP[r][p00][lane + 32] + w01 * g_featP[r][p01][lane + 32]
           + w10 * g_featP[r][p10][lane + 32] + w11 * g_featP[r][p11][lane + 32];
        v0 = w00 * g_valP[r][p00][lane]       + w01 * g_valP[r][p01][lane]
           + w10 * g_valP[r][p10][lane]       + w11 * g_valP[r][p11][lane];
        v1 = w00 * g_valP[r][p00][lane + 32]  + w01 * g_valP[r][p01][lane + 32]
           + w10 * g_valP[r][p10][lane + 32]  + w11 * g_valP[r][p11][lane + 32];
    }
    float ss = f0 * f0 + f1 * f1;
    #pragma unroll
    for (int off = 16; off > 0; off >>= 1) ss += __shfl_xor_sync(0xffffffffu, ss, off);
    float inv = 1.0f / fmaxf(sqrtf(ss), 1e-12f);
    float a = sim_alpha[0] * inv;
    __half h0, l0, h1, l1;
    split_f16(a * f0, h0, l0);
    split_f16(a * f1, h1, l1);
    sh_h[w][lane]      = h0;  sh_l[w][lane]      = l0;
    sh_h[w][lane + 32] = h1;  sh_l[w][lane + 32] = l1;
    __syncwarp();
    if (lane < 16) {
        int s = lane >> 2, tt = lane & 3;
        int kb = s * 16 + 2 * tt;
        uint32_t b0h = pack_h2(sh_h[w][kb],     sh_h[w][kb + 1]);
        uint32_t b1h = pack_h2(sh_h[w][kb + 8], sh_h[w][kb + 9]);
        uint32_t b0l = pack_h2(sh_l[w][kb],     sh_l[w][kb + 1]);
        uint32_t b1l = pack_h2(sh_l[w][kb + 8], sh_l[w][kb + 9]);
        g_bp[r][m][lane] = make_float4(__uint_as_float(b0h), __uint_as_float(b1h),
                                       __uint_as_float(b0l), __uint_as_float(b1l));
    }
    if (m < cnt) {
        g_vc[r][m][lane]      = v0;
        g_vc[r][m][lane + 32] = v1;
    }
}

// ---------------- Kernel E: fp16 3-term m16n8k16 GEMM + fused argmax, atomicMax merge ----------------
#define BSTR 20
__global__ __launch_bounds__(256, 2) void kE5() {
    extern __shared__ float4 Bp[];
    int tid = threadIdx.x;
    int wid = tid >> 5, lane = tid & 31;
    int gid = lane >> 2, t4 = lane & 3;
    int r = blockIdx.z, y = blockIdx.y;
    int k0 = blockIdx.x * 128;
    int cnt = min(g_cnt[r], MCAP);
    int Mr = cnt + (cnt < MCAP ? 1 : 0);
    int nsub = (Mr + 127) >> 7;
    int row0 = k0 + wid * 16 + gid;
    int row1 = row0 + 8;

    float best0 = -FLT_MAX, best1 = -FLT_MAX;
    int   bi0 = 0x7fffffff, bi1 = 0x7fffffff;

    if (y < nsub) {
        uint32_t Ah[4][4], Al[4][4];
        #pragma unroll
        for (int s = 0; s < 4; s++) {
            int kk = s * 16 + 2 * t4;
            Ah[s][0] = *reinterpret_cast<const uint32_t*>(&g_fh16[r][row0][kk]);
            Ah[s][1] = *reinterpret_cast<const uint32_t*>(&g_fh16[r][row1][kk]);
            Ah[s][2] = *reinterpret_cast<const uint32_t*>(&g_fh16[r][row0][kk + 8]);
            Ah[s][3] = *reinterpret_cast<const uint32_t*>(&g_fh16[r][row1][kk + 8]);
            Al[s][0] = *reinterpret_cast<const uint32_t*>(&g_fl16[r][row0][kk]);
            Al[s][1] = *reinterpret_cast<const uint32_t*>(&g_fl16[r][row1][kk]);
            Al[s][2] = *reinterpret_cast<const uint32_t*>(&g_fl16[r][row0][kk + 8]);
            Al[s][3] = *reinterpret_cast<const uint32_t*>(&g_fl16[r][row1][kk + 8]);
        }

        for (int ns = y; ns < nsub; ns += NCH2) {
            int m0 = ns * 128;
            __syncthreads();
            #pragma unroll
            for (int it = 0; it < 8; it++) {
                int e = tid + it * 256;
                int brow = e >> 4, slot = e & 15;
                Bp[brow * BSTR + slot] = g_bp[r][m0 + brow][slot];
            }
            __syncthreads();

            #pragma unroll
            for (int half = 0; half < 2; half++) {
                float c[8][4];
                #pragma unroll
                for (int nt = 0; nt < 8; nt++)
                    #pragma unroll
                    for (int j = 0; j < 4; j++) c[nt][j] = 0.f;

                const float4* bbase = Bp + (half * 64 + gid) * BSTR + t4;
                #pragma unroll
                for (int s = 0; s < 4; s++) {
                    const float4* bks = bbase + s * 4;
                    #pragma unroll
                    for (int nt = 0; nt < 8; nt++) {
                        float4 v = bks[nt * 8 * BSTR];
                        uint32_t b0h = __float_as_uint(v.x);
                        uint32_t b1h = __float_as_uint(v.y);
                        uint32_t b0l = __float_as_uint(v.z);
                        uint32_t b1l = __float_as_uint(v.w);
                        mma_f16(c[nt], Ah[s], b0h, b1h);
                        mma_f16(c[nt], Ah[s], b0l, b1l);
                        mma_f16(c[nt], Al[s], b0h, b1h);
                    }
                }

                int cbase = m0 + half * 64 + t4 * 2;
                #pragma unroll
                for (int nt = 0; nt < 8; nt++) {
                    int col0 = cbase + nt * 8;
                    int col1 = col0 + 1;
                    if (col0 < Mr) {
                        if (c[nt][0] > best0) { best0 = c[nt][0]; bi0 = col0; }
                        if (c[nt][2] > best1) { best1 = c[nt][2]; bi1 = col0; }
                    }
                    if (col1 < Mr) {
                        if (c[nt][1] > best0) { best0 = c[nt][1]; bi0 = col1; }
                        if (c[nt][3] > best1) { best1 = c[nt][3]; bi1 = col1; }
                    }
                }
            }
        }

        #pragma unroll
        for (int off = 1; off <= 2; off <<= 1) {
            float ov0 = __shfl_xor_sync(0xffffffffu, best0, off);
            int   om0 = __shfl_xor_sync(0xffffffffu, bi0,   off);
            float ov1 = __shfl_xor_sync(0xffffffffu, best1, off);
            int   om1 = __shfl_xor_sync(0xffffffffu, bi1,   off);
            if (ov0 > best0 || (ov0 == best0 && om0 < bi0)) { best0 = ov0; bi0 = om0; }
            if (ov1 > best1 || (ov1 == best1 && om1 < bi1)) { best1 = ov1; bi1 = om1; }
        }
        if (t4 == 0) {
            atomicMax(&g_best[r][row0], packbm(best0, bi0));
            atomicMax(&g_best[r][row1], packbm(best1, bi1));
        }
    }
}

// ---------------- Kernel M: decode merged argmax, sigmoid, scatter-aggregate ----------------
__global__ __launch_bounds__(256) void kM(const float* __restrict__ sim_beta) {
    int r = blockIdx.y;
    int warp = threadIdx.x >> 5, lane = threadIdx.x & 31;
    int col = blockIdx.x * 8 + warp;
    unsigned int cnt = (unsigned int)min(g_cnt[r], MCAP);
    unsigned long long pk = g_best[r][col];
    unsigned int m = ~(unsigned int)(pk & 0xFFFFFFFFull);
    if (m >= cnt) return;    // dead row won, empty, or uninitialized
    uint32_t fk = (uint32_t)(pk >> 32);
    uint32_t vb = (fk & 0x80000000u) ? (fk & 0x7fffffffu) : ~fk;
    float v = __uint_as_float(vb);
    float s = sim_beta[0] + v * g_invx[r][col];
    float sim = 1.0f / (1.0f + __expf(-s));
    atomicAdd(&g_agg[r][m][lane],      sim * g_valP[r][col][lane]);
    atomicAdd(&g_agg[r][m][lane + 32], sim * g_valP[r][col][lane + 32]);
    if (lane == 0) atomicAdd(&g_den[r][m], sim);
}

// ---------------- Kernel F: per-point output assembly + projection ----------------
__global__ __launch_bounds__(256) void kF(const float* __restrict__ Wp,
                                          const float* __restrict__ bp,
                                          float* __restrict__ out) {
    __shared__ float so[64][65];
    __shared__ float wp[64][65];
    __shared__ float bsh[64];
    __shared__ int   fl[64];
    int tx = threadIdx.x;
    int n0 = blockIdx.x * 64;
    #pragma unroll
    for (int j = 0; j < 16; j++) {
        int idx = tx + j * 256;
        int o = idx >> 6, c = idx & 63;
        wp[c][o] = Wp[idx];
    }
    if (tx < 64) { bsh[tx] = bp[tx]; fl[tx] = 0; }
    __syncthreads();
    {
        int pl = tx >> 2, cg = tx & 3;
        int n = n0 + pl;
        int r = g_pr[n];
        int lf = 0;
        if (r >= 0) {
            int pos = min(g_ppos[n], MCAP - 1);
            float den = g_den[r][pos] + 1.0f;
            #pragma unroll
            for (int j = 0; j < 16; j++) {
                int c = cg * 16 + j;
                float ov = (g_agg[r][pos][c] + g_vc[r][pos][c]) / den;
                so[pl][c] = ov;
                if (ov != 0.0f) lf = 1;
            }
        } else {
            #pragma unroll
            for (int j = 0; j < 16; j++) so[pl][cg * 16 + j] = 0.0f;
        }
        if (lf) atomicOr(&fl[pl], 1);
    }
    __syncthreads();
    int pl = tx & 63, og = tx >> 6;
    float mask = fl[pl] ? 1.0f : 0.0f;
    float acc[16];
    #pragma unroll
    for (int i = 0; i < 16; i++) acc[i] = 0.f;
    #pragma unroll
    for (int c = 0; c < 64; c++) {
        float xv = so[pl][c];
        #pragma unroll
        for (int i = 0; i < 16; i++) acc[i] += xv * wp[c][og * 16 + i];
    }
    #pragma unroll
    for (int i = 0; i < 16; i++) {
        int o = og * 16 + i;
        out[o * NP + n0 + pl] = (acc[i] + bsh[o]) * mask;
    }
}

// ---------------- launch ----------------
#define KE_SMEM (128 * BSTR * 16)

extern "C" void kernel_launch(void* const* d_in, const int* in_sizes, int n_in,
                              void* d_out, int out_size) {
    const float* points    = (const float*)d_in[0];
    const float* x         = (const float*)d_in[1];
    const float* W_f       = (const float*)d_in[2];
    const float* b_f       = (const float*)d_in[3];
    const float* W_v       = (const float*)d_in[4];
    const float* b_v       = (const float*)d_in[5];
    const float* W_proj    = (const float*)d_in[6];
    const float* b_proj    = (const float*)d_in[7];
    const float* sim_alpha = (const float*)d_in[8];
    const float* sim_beta  = (const float*)d_in[9];
    float* out = (float*)d_out;

    cudaFuncSetAttribute(kE5, cudaFuncAttributeMaxDynamicSharedMemorySize, KE_SMEM);

    kA<<<217, 256>>>(x, W_f, b_f, W_v, b_v, points);
    kD<<<dim3(MPAD / 8, R4), 256>>>(sim_alpha);
    kE5<<<dim3(KP / 128, NCH2, R4), 256, KE_SMEM>>>();
    kM<<<dim3(KP / 8, R4), 256>>>(sim_beta);
    kF<<<NP / 64, 256>>>(W_proj, b_proj, out);
}

// round 17
// speedup vs baseline: 1.1125x; 1.0386x over previous
#include <cuda_runtime.h>
#include <cuda_fp16.h>
#include <math.h>
#include <float.h>
#include <stdint.h>

// ---------------- problem constants ----------------
#define R4    4           // fold regions
#define HH    64          // input feature H
#define WW0   216         // input feature W
#define HWP   (HH*WW0)    // 13824 pixels
#define HF    32          // folded H
#define WF    108         // folded W
#define KP    (HF*WF)     // 3456 pixels per region
#define C64   64          // channels
#define NP    8192        // points
#define MCAP  4096        // M = N / FOLD_H
#define MPAD  4608        // padded rows for centers
#define NCH2  5           // interleaved subtile stride

// ---------------- scratch (device globals; no allocation) ----------------
__device__ float  g_featP[R4][KP][C64];   // folded feat, pixel-major
__device__ float  g_valP [R4][KP][C64];   // folded value, pixel-major
__device__ __half g_fh16 [R4][KP][C64];   // feat fp16-hi
__device__ __half g_fl16 [R4][KP][C64];   // feat fp16-lo
__device__ float  g_invx [R4][KP];        // 1/max(||feat_pixel||,1e-12)
__device__ float4 g_bp   [R4][MPAD][16];  // centers packed: slot (s,t4) -> {b0h,b1h,b0l,b1l} half2s
__device__ float  g_vc   [R4][MCAP][C64]; // value centers
__device__ int    g_cnt  [R4];
__device__ float  g_ppx  [R4][MCAP];
__device__ float  g_ppy  [R4][MCAP];
__device__ int    g_pr   [NP];
__device__ int    g_ppos [NP];
__device__ unsigned long long g_best[R4][KP];  // packed (ordered-float << 32) | ~m
__device__ float  g_agg  [R4][MCAP][C64];
__device__ float  g_den  [R4][MCAP];

// ---------------- helpers ----------------
__device__ __forceinline__ void split_f16(float v, __half& hi, __half& lo) {
    hi = __float2half_rn(v);
    lo = __float2half_rn(v - __half2float(hi));
}
__device__ __forceinline__ uint32_t pack_h2(__half a, __half b) {
    __half2 h = __halves2half2(a, b);
    return *reinterpret_cast<uint32_t*>(&h);
}
__device__ __forceinline__ void mma_f16(float c[4], const uint32_t a[4], uint32_t b0, uint32_t b1) {
    asm volatile(
        "mma.sync.aligned.m16n8k16.row.col.f32.f16.f16.f32 "
        "{%0,%1,%2,%3}, {%4,%5,%6,%7}, {%8,%9}, {%0,%1,%2,%3};"
        : "+f"(c[0]), "+f"(c[1]), "+f"(c[2]), "+f"(c[3])
        : "r"(a[0]), "r"(a[1]), "r"(a[2]), "r"(a[3]), "r"(b0), "r"(b1));
}
__device__ __forceinline__ int region_of(float px, float py) {
    if (px > 0.0f && px <= 1296.0f && py > 0.0f && py <= 384.0f)
        return ((py > 192.0f) ? 2 : 0) + ((px > 648.0f) ? 1 : 0);
    return -1;
}
__device__ __forceinline__ unsigned long long packbm(float v, int m) {
    uint32_t b = __float_as_uint(v);
    uint32_t fk = (b & 0x80000000u) ? ~b : (b | 0x80000000u);   // order-preserving
    return ((unsigned long long)fk << 32) | (uint32_t)(~(uint32_t)m);
}
__device__ __forceinline__ void dep_sync() { cudaGridDependencySynchronize(); }

// ---------------- Kernel A: 1x1 conv + fold + fp16 split + inv-norm; block 216 = point partition ----------------
__global__ __launch_bounds__(256) void kA(const float* __restrict__ x,
                                          const float* __restrict__ Wf, const float* __restrict__ bf,
                                          const float* __restrict__ Wv, const float* __restrict__ bv,
                                          const float* __restrict__ pts) {
    int tx = threadIdx.x;

    if (blockIdx.x == 216) {
        __shared__ unsigned long long warpTot[8];
        __shared__ unsigned long long baseSh;
        int widx = tx >> 5, lane = tx & 31;
        if (tx == 0) baseSh = 0ull;
        __syncthreads();
        for (int ch = 0; ch < 32; ch++) {
            int n = ch * 256 + tx;
            float px = pts[2 * n], py = pts[2 * n + 1];
            int ri = region_of(px, py);
            unsigned long long item = (ri >= 0) ? (1ull << (16 * ri)) : 0ull;
            unsigned long long incl = item;
            #pragma unroll
            for (int off = 1; off < 32; off <<= 1) {
                unsigned long long v = __shfl_up_sync(0xffffffffu, incl, off);
                if (lane >= off) incl += v;
            }
            if (lane == 31) warpTot[widx] = incl;
            unsigned long long base = baseSh;
            __syncthreads();
            unsigned long long wpre = 0ull;
            for (int w = 0; w < widx; w++) wpre += warpTot[w];
            unsigned long long ex = base + wpre + (incl - item);
            if (ri >= 0) {
                int pos = (int)((ex >> (16 * ri)) & 0xFFFF);
                g_pr[n] = ri; g_ppos[n] = pos;
                if (pos < MCAP) { g_ppx[ri][pos] = px; g_ppy[ri][pos] = py; }
            } else { g_pr[n] = -1; g_ppos[n] = 0; }
            if (tx == 255) baseSh = base + wpre + incl;
            __syncthreads();
        }
        if (tx == 0) {
            unsigned long long tot = baseSh;
            #pragma unroll
            for (int r = 0; r < 4; r++) g_cnt[r] = (int)((tot >> (16 * r)) & 0xFFFF);
        }
        return;
    }

    __shared__ float xs [64][68];
    __shared__ float wfs[64][68];
    __shared__ float wvs[64][68];
    int p0 = blockIdx.x * 64;

    #pragma unroll
    for (int j = 0; j < 16; j++) {
        int idx = tx + j * 256;
        int o = idx >> 6, c = idx & 63;
        wfs[c][o] = Wf[idx];
        wvs[c][o] = Wv[idx];
    }
    #pragma unroll
    for (int j = 0; j < 16; j++) {
        int idx = tx + j * 256;
        int c = idx >> 6, pl = idx & 63;
        xs[c][pl] = x[c * HWP + p0 + pl];
    }
    __syncthreads();
    int o  = tx & 63;
    int pg = tx >> 6;
    float accf[16], accv[16];
    float bfo = bf[o], bvo = bv[o];
    #pragma unroll
    for (int i = 0; i < 16; i++) { accf[i] = bfo; accv[i] = bvo; }
    #pragma unroll
    for (int c = 0; c < 64; c++) {
        float wfv = wfs[c][o];
        float wvv = wvs[c][o];
        float4 x0 = *reinterpret_cast<const float4*>(&xs[c][pg * 16]);
        float4 x1 = *reinterpret_cast<const float4*>(&xs[c][pg * 16 + 4]);
        float4 x2 = *reinterpret_cast<const float4*>(&xs[c][pg * 16 + 8]);
        float4 x3 = *reinterpret_cast<const float4*>(&xs[c][pg * 16 + 12]);
        float xv[16] = {x0.x, x0.y, x0.z, x0.w, x1.x, x1.y, x1.z, x1.w,
                        x2.x, x2.y, x2.z, x2.w, x3.x, x3.y, x3.z, x3.w};
        #pragma unroll
        for (int i = 0; i < 16; i++) {
            accf[i] += wfv * xv[i];
            accv[i] += wvv * xv[i];
        }
    }
    #pragma unroll
    for (int i = 0; i < 16; i++) {
        int p = p0 + pg * 16 + i;
        int h = p / WW0, w = p % WW0;
        int r = ((h >= HF) ? 2 : 0) + ((w >= WF) ? 1 : 0);
        int loc = (h & 31) * WF + (w >= WF ? w - WF : w);
        g_featP[r][loc][o] = accf[i];
        g_valP [r][loc][o] = accv[i];
        __half hh, ll;
        split_f16(accf[i], hh, ll);
        g_fh16[r][loc][o] = hh;
        g_fl16[r][loc][o] = ll;
    }
    __syncthreads();
    #pragma unroll
    for (int i = 0; i < 16; i++) wfs[pg * 16 + i][o] = accf[i] * accf[i];
    __syncthreads();
    {
        int pl = tx >> 2, q = tx & 3;
        float s = 0.f;
        #pragma unroll
        for (int j = 0; j < 16; j++) s += wfs[pl][q * 16 + j];
        s += __shfl_xor_sync(0xffffffffu, s, 1);
        s += __shfl_xor_sync(0xffffffffu, s, 2);
        if (q == 0) {
            int p = p0 + pl;
            int h = p / WW0, w = p % WW0;
            int r = ((h >= HF) ? 2 : 0) + ((w >= WF) ? 1 : 0);
            int loc = (h & 31) * WF + (w >= WF ? w - WF : w);
            g_invx[r][loc] = 1.0f / fmaxf(sqrtf(s), 1e-12f);
        }
    }
}

// ---------------- Kernel D: pre-sync zero duty, then bilinear gather + fp16 pack ----------------
__global__ __launch_bounds__(256) void kD(const float* __restrict__ sim_alpha) {
    __shared__ __half sh_h[8][64];
    __shared__ __half sh_l[8][64];
    int r = blockIdx.y;
    // independent prologue (before grid-dependency sync): zero agg/den, init g_best
    if (blockIdx.x >= 288) {
        int local = (blockIdx.x - 288) * 256 + threadIdx.x;   // 0..73727 per region
        if (local < KP) g_best[r][local] = 0ull;              // below all real packed keys
        int slice = (blockIdx.x - 288) + 288 * r;             // 0..1151
        int t = slice * 256 + threadIdx.x;                    // 0..294911
        const int nagg4 = R4 * MCAP * C64 / 4;                // 262144
        if (t < nagg4) reinterpret_cast<float4*>(&g_agg[0][0][0])[t] = make_float4(0.f, 0.f, 0.f, 0.f);
        if (t < R4 * MCAP) (&g_den[0][0])[t] = 0.f;
    }
    dep_sync();                                               // wait for kA outputs
    int cnt = min(g_cnt[r], MCAP);
    int Mr = cnt + (cnt < MCAP ? 1 : 0);
    int lim = ((Mr + 127) >> 7) << 7;
    int w = threadIdx.x >> 5;
    int m = blockIdx.x * 8 + w;
    int lane = threadIdx.x & 31;
    if (m >= lim) return;
    if (m >= Mr) {
        if (lane < 16) g_bp[r][m][lane] = make_float4(0.f, 0.f, 0.f, 0.f);
        return;
    }
    float f0, f1, v0 = 0.f, v1 = 0.f;
    if (m == cnt) {
        f0 = g_featP[r][0][lane];
        f1 = g_featP[r][0][lane + 32];
    } else {
        float px = g_ppx[r][m], py = g_ppy[r][m];
        float gx = ((px / 1295.0f) * 2.0f - 1.0f + 1.0f) * 54.0f - 0.5f;
        float gy = ((py / 383.0f)  * 2.0f - 1.0f + 1.0f) * 16.0f - 0.5f;
        float x0 = floorf(gx), y0 = floorf(gy);
        float wx = gx - x0, wy = gy - y0;
        int ix0 = (int)fminf(fmaxf(x0,        0.f), 107.f);
        int ix1 = (int)fminf(fmaxf(x0 + 1.0f, 0.f), 107.f);
        int iy0 = (int)fminf(fmaxf(y0,        0.f), 31.f);
        int iy1 = (int)fminf(fmaxf(y0 + 1.0f, 0.f), 31.f);
        float w00 = (1.f - wx) * (1.f - wy), w01 = wx * (1.f - wy);
        float w10 = (1.f - wx) * wy,         w11 = wx * wy;
        int p00 = iy0 * WF + ix0, p01 = iy0 * WF + ix1;
        int p10 = iy1 * WF + ix0, p11 = iy1 * WF + ix1;
        f0 = w00 * g_featP[r][p00][lane]      + w01 * g_featP[r][p01][lane]
           + w10 * g_featP[r][p10][lane]      + w11 * g_featP[r][p11][lane];
        f1 = w00 * g_featP[r][p00][lane + 32] + w01 * g_featP[r][p01][lane + 32]
           + w10 * g_featP[r][p10][lane + 32] + w11 * g_featP[r][p11][lane + 32];
        v0 = w00 * g_valP[r][p00][lane]       + w01 * g_valP[r][p01][lane]
           + w10 * g_valP[r][p10][lane]       + w11 * g_valP[r][p11][lane];
        v1 = w00 * g_valP[r][p00][lane + 32]  + w01 * g_valP[r][p01][lane + 32]
           + w10 * g_valP[r][p10][lane + 32]  + w11 * g_valP[r][p11][lane + 32];
    }
    float ss = f0 * f0 + f1 * f1;
    #pragma unroll
    for (int off = 16; off > 0; off >>= 1) ss += __shfl_xor_sync(0xffffffffu, ss, off);
    float inv = 1.0f / fmaxf(sqrtf(ss), 1e-12f);
    float a = sim_alpha[0] * inv;
    __half h0, l0, h1, l1;
    split_f16(a * f0, h0, l0);
    split_f16(a * f1, h1, l1);
    sh_h[w][lane]      = h0;  sh_l[w][lane]      = l0;
    sh_h[w][lane + 32] = h1;  sh_l[w][lane + 32] = l1;
    __syncwarp();
    if (lane < 16) {
        int s = lane >> 2, tt = lane & 3;
        int kb = s * 16 + 2 * tt;
        uint32_t b0h = pack_h2(sh_h[w][kb],     sh_h[w][kb + 1]);
        uint32_t b1h = pack_h2(sh_h[w][kb + 8], sh_h[w][kb + 9]);
        uint32_t b0l = pack_h2(sh_l[w][kb],     sh_l[w][kb + 1]);
        uint32_t b1l = pack_h2(sh_l[w][kb + 8], sh_l[w][kb + 9]);
        g_bp[r][m][lane] = make_float4(__uint_as_float(b0h), __uint_as_float(b1h),
                                       __uint_as_float(b0l), __uint_as_float(b1l));
    }
    if (m < cnt) {
        g_vc[r][m][lane]      = v0;
        g_vc[r][m][lane + 32] = v1;
    }
}

// ---------------- Kernel E: fp16 3-term m16n8k16 GEMM + fused argmax, atomicMax merge ----------------
#define BSTR 20
__global__ __launch_bounds__(256, 2) void kE5() {
    extern __shared__ float4 Bp[];
    dep_sync();                          // wait for kD outputs
    int tid = threadIdx.x;
    int wid = tid >> 5, lane = tid & 31;
    int gid = lane >> 2, t4 = lane & 3;
    int r = blockIdx.z, y = blockIdx.y;
    int k0 = blockIdx.x * 128;
    int cnt = min(g_cnt[r], MCAP);
    int Mr = cnt + (cnt < MCAP ? 1 : 0);
    int nsub = (Mr + 127) >> 7;
    int row0 = k0 + wid * 16 + gid;
    int row1 = row0 + 8;

    float best0 = -FLT_MAX, best1 = -FLT_MAX;
    int   bi0 = 0x7fffffff, bi1 = 0x7fffffff;

    if (y < nsub) {
        uint32_t Ah[4][4], Al[4][4];
        #pragma unroll
        for (int s = 0; s < 4; s++) {
            int kk = s * 16 + 2 * t4;
            Ah[s][0] = *reinterpret_cast<const uint32_t*>(&g_fh16[r][row0][kk]);
            Ah[s][1] = *reinterpret_cast<const uint32_t*>(&g_fh16[r][row1][kk]);
            Ah[s][2] = *reinterpret_cast<const uint32_t*>(&g_fh16[r][row0][kk + 8]);
            Ah[s][3] = *reinterpret_cast<const uint32_t*>(&g_fh16[r][row1][kk + 8]);
            Al[s][0] = *reinterpret_cast<const uint32_t*>(&g_fl16[r][row0][kk]);
            Al[s][1] = *reinterpret_cast<const uint32_t*>(&g_fl16[r][row1][kk]);
            Al[s][2] = *reinterpret_cast<const uint32_t*>(&g_fl16[r][row0][kk + 8]);
            Al[s][3] = *reinterpret_cast<const uint32_t*>(&g_fl16[r][row1][kk + 8]);
        }

        for (int ns = y; ns < nsub; ns += NCH2) {
            int m0 = ns * 128;
            __syncthreads();
            #pragma unroll
            for (int it = 0; it < 8; it++) {
                int e = tid + it * 256;
                int brow = e >> 4, slot = e & 15;
                Bp[brow * BSTR + slot] = g_bp[r][m0 + brow][slot];
            }
            __syncthreads();

            #pragma unroll
            for (int half = 0; half < 2; half++) {
                float c[8][4];
                #pragma unroll
                for (int nt = 0; nt < 8; nt++)
                    #pragma unroll
                    for (int j = 0; j < 4; j++) c[nt][j] = 0.f;

                const float4* bbase = Bp + (half * 64 + gid) * BSTR + t4;
                #pragma unroll
                for (int s = 0; s < 4; s++) {
                    const float4* bks = bbase + s * 4;
                    #pragma unroll
                    for (int nt = 0; nt < 8; nt++) {
                        float4 v = bks[nt * 8 * BSTR];
                        uint32_t b0h = __float_as_uint(v.x);
                        uint32_t b1h = __float_as_uint(v.y);
                        uint32_t b0l = __float_as_uint(v.z);
                        uint32_t b1l = __float_as_uint(v.w);
                        mma_f16(c[nt], Ah[s], b0h, b1h);
                        mma_f16(c[nt], Ah[s], b0l, b1l);
                        mma_f16(c[nt], Al[s], b0h, b1h);
                    }
                }

                int cbase = m0 + half * 64 + t4 * 2;
                #pragma unroll
                for (int nt = 0; nt < 8; nt++) {
                    int col0 = cbase + nt * 8;
                    int col1 = col0 + 1;
                    if (col0 < Mr) {
                        if (c[nt][0] > best0) { best0 = c[nt][0]; bi0 = col0; }
                        if (c[nt][2] > best1) { best1 = c[nt][2]; bi1 = col0; }
                    }
                    if (col1 < Mr) {
                        if (c[nt][1] > best0) { best0 = c[nt][1]; bi0 = col1; }
                        if (c[nt][3] > best1) { best1 = c[nt][3]; bi1 = col1; }
                    }
                }
            }
        }

        #pragma unroll
        for (int off = 1; off <= 2; off <<= 1) {
            float ov0 = __shfl_xor_sync(0xffffffffu, best0, off);
            int   om0 = __shfl_xor_sync(0xffffffffu, bi0,   off);
            float ov1 = __shfl_xor_sync(0xffffffffu, best1, off);
            int   om1 = __shfl_xor_sync(0xffffffffu, bi1,   off);
            if (ov0 > best0 || (ov0 == best0 && om0 < bi0)) { best0 = ov0; bi0 = om0; }
            if (ov1 > best1 || (ov1 == best1 && om1 < bi1)) { best1 = ov1; bi1 = om1; }
        }
        if (t4 == 0) {
            atomicMax(&g_best[r][row0], packbm(best0, bi0));
            atomicMax(&g_best[r][row1], packbm(best1, bi1));
        }
    }
}

// ---------------- Kernel M: decode merged argmax, sigmoid, scatter-aggregate ----------------
__global__ __launch_bounds__(256) void kM(const float* __restrict__ sim_beta) {
    dep_sync();                          // wait for kE outputs
    int r = blockIdx.y;
    int warp = threadIdx.x >> 5, lane = threadIdx.x & 31;
    int col = blockIdx.x * 8 + warp;
    unsigned int cnt = (unsigned int)min(g_cnt[r], MCAP);
    unsigned long long pk = g_best[r][col];
    unsigned int m = ~(unsigned int)(pk & 0xFFFFFFFFull);
    if (m >= cnt) return;    // dead row won, empty, or uninitialized
    uint32_t fk = (uint32_t)(pk >> 32);
    uint32_t vb = (fk & 0x80000000u) ? (fk & 0x7fffffffu) : ~fk;
    float v = __uint_as_float(vb);
    float s = sim_beta[0] + v * g_invx[r][col];
    float sim = 1.0f / (1.0f + __expf(-s));
    atomicAdd(&g_agg[r][m][lane],      sim * g_valP[r][col][lane]);
    atomicAdd(&g_agg[r][m][lane + 32], sim * g_valP[r][col][lane + 32]);
    if (lane == 0) atomicAdd(&g_den[r][m], sim);
}

// ---------------- Kernel F: per-point output assembly + projection ----------------
__global__ __launch_bounds__(256) void kF(const float* __restrict__ Wp,
                                          const float* __restrict__ bp,
                                          float* __restrict__ out) {
    __shared__ float so[64][65];
    __shared__ float wp[64][65];
    __shared__ float bsh[64];
    __shared__ int   fl[64];
    int tx = threadIdx.x;
    int n0 = blockIdx.x * 64;
    // independent prologue: load weights/bias (harness inputs) before dependency sync
    #pragma unroll
    for (int j = 0; j < 16; j++) {
        int idx = tx + j * 256;
        int o = idx >> 6, c = idx & 63;
        wp[c][o] = Wp[idx];
    }
    if (tx < 64) { bsh[tx] = bp[tx]; fl[tx] = 0; }
    dep_sync();                          // wait for kM outputs
    __syncthreads();
    {
        int pl = tx >> 2, cg = tx & 3;
        int n = n0 + pl;
        int r = g_pr[n];
        int lf = 0;
        if (r >= 0) {
            int pos = min(g_ppos[n], MCAP - 1);
            float den = g_den[r][pos] + 1.0f;
            #pragma unroll
            for (int j = 0; j < 16; j++) {
                int c = cg * 16 + j;
                float ov = (g_agg[r][pos][c] + g_vc[r][pos][c]) / den;
                so[pl][c] = ov;
                if (ov != 0.0f) lf = 1;
            }
        } else {
            #pragma unroll
            for (int j = 0; j < 16; j++) so[pl][cg * 16 + j] = 0.0f;
        }
        if (lf) atomicOr(&fl[pl], 1);
    }
    __syncthreads();
    int pl = tx & 63, og = tx >> 6;
    float mask = fl[pl] ? 1.0f : 0.0f;
    float acc[16];
    #pragma unroll
    for (int i = 0; i < 16; i++) acc[i] = 0.f;
    #pragma unroll
    for (int c = 0; c < 64; c++) {
        float xv = so[pl][c];
        #pragma unroll
        for (int i = 0; i < 16; i++) acc[i] += xv * wp[c][og * 16 + i];
    }
    #pragma unroll
    for (int i = 0; i < 16; i++) {
        int o = og * 16 + i;
        out[o * NP + n0 + pl] = (acc[i] + bsh[o]) * mask;
    }
}

// ---------------- launch: single stream, PDL-chained ----------------
#define KE_SMEM (128 * BSTR * 16)

template <typename... Args>
static inline void launch_pdl(void (*kern)(Args...), dim3 grid, dim3 block, size_t smem, Args... args) {
    cudaLaunchConfig_t cfg = {};
    cfg.gridDim = grid;
    cfg.blockDim = block;
    cfg.dynamicSmemBytes = smem;
    cfg.stream = 0;
    cudaLaunchAttribute attr[1];
    attr[0].id = cudaLaunchAttributeProgrammaticStreamSerialization;
    attr[0].val.programmaticStreamSerializationAllowed = 1;
    cfg.attrs = attr;
    cfg.numAttrs = 1;
    cudaLaunchKernelEx(&cfg, kern, args...);
}

extern "C" void kernel_launch(void* const* d_in, const int* in_sizes, int n_in,
                              void* d_out, int out_size) {
    const float* points    = (const float*)d_in[0];
    const float* x         = (const float*)d_in[1];
    const float* W_f       = (const float*)d_in[2];
    const float* b_f       = (const float*)d_in[3];
    const float* W_v       = (const float*)d_in[4];
    const float* b_v       = (const float*)d_in[5];
    const float* W_proj    = (const float*)d_in[6];
    const float* b_proj    = (const float*)d_in[7];
    const float* sim_alpha = (const float*)d_in[8];
    const float* sim_beta  = (const float*)d_in[9];
    float* out = (float*)d_out;

    cudaFuncSetAttribute(kE5, cudaFuncAttributeMaxDynamicSharedMemorySize, KE_SMEM);

    kA<<<217, 256>>>(x, W_f, b_f, W_v, b_v, points);
    launch_pdl(kD, dim3(MPAD / 8, R4), dim3(256), 0, sim_alpha);
    launch_pdl(kE5, dim3(KP / 128, NCH2, R4), dim3(256), (size_t)KE_SMEM);
    launch_pdl(kM, dim3(KP / 8, R4), dim3(256), 0, sim_beta);
    launch_pdl(kF, dim3(NP / 64), dim3(256), 0, W_proj, b_proj, out);
}